// round 1
// baseline (speedup 1.0000x reference)
#include <cuda_runtime.h>

// Shapes (fixed): B=8, L=256, F=512, U=512.
// inputs [8,256,512], Wq [512,512], Wk [512,512], Wv [512,1], bh [512], ba [1]
// out [8,256,512] float32.

#define Bn 8
#define Ln 256
#define Fn 512
#define Un 512
#define Mn (Bn*Ln)   // 2048

// Scratch: Q [2048,512] row-major, KT [8][512][256] (K + bh, transposed per batch)
__device__ float g_Q[Mn * Un];
__device__ float g_KT[Bn * Un * Ln];

__device__ __forceinline__ float tanh_approx(float x) {
    float y;
    asm("tanh.approx.f32 %0, %1;" : "=f"(y) : "f"(x));
    return y;
}

// ---------------------------------------------------------------------------
// Kernel A: dual SGEMM. Computes Q = X*Wq and KT = transpose(X*Wk + bh).
// 64x64 tile, BK=16, 256 threads, 4x4 micro-tile per thread per output.
// A tile is loaded once and shared by both B operands.
// ---------------------------------------------------------------------------
#define BM 64
#define BN 64
#define BK 16

__global__ __launch_bounds__(256) void proj_kernel(
    const float* __restrict__ X,    // [2048,512]
    const float* __restrict__ Wq,   // [512,512]
    const float* __restrict__ Wk,   // [512,512]
    const float* __restrict__ bh)   // [512]
{
    __shared__ float As[BK][BM];
    __shared__ float B1s[BK][BN];
    __shared__ float B2s[BK][BN];

    const int tid = threadIdx.x;
    const int tx = tid & 15;   // n direction
    const int ty = tid >> 4;   // m direction
    const int m0 = blockIdx.y * BM;
    const int n0 = blockIdx.x * BN;

    float acc1[4][4], acc2[4][4];
#pragma unroll
    for (int i = 0; i < 4; i++)
#pragma unroll
        for (int j = 0; j < 4; j++) { acc1[i][j] = 0.f; acc2[i][j] = 0.f; }

    // A tile loader: 64 rows x 16 k, one float4 per thread
    const int a_row = tid >> 2;
    const int a_k4  = (tid & 3) * 4;
    // B tile loader: 16 k x 64 n, one float4 per thread
    const int b_k  = tid >> 4;
    const int b_n4 = (tid & 15) * 4;

    for (int k0 = 0; k0 < Fn; k0 += BK) {
        float4 av  = *(const float4*)&X [(m0 + a_row) * Fn + k0 + a_k4];
        float4 bv1 = *(const float4*)&Wq[(k0 + b_k) * Un + n0 + b_n4];
        float4 bv2 = *(const float4*)&Wk[(k0 + b_k) * Un + n0 + b_n4];

        As[a_k4 + 0][a_row] = av.x;
        As[a_k4 + 1][a_row] = av.y;
        As[a_k4 + 2][a_row] = av.z;
        As[a_k4 + 3][a_row] = av.w;
        *(float4*)&B1s[b_k][b_n4] = bv1;
        *(float4*)&B2s[b_k][b_n4] = bv2;
        __syncthreads();

#pragma unroll
        for (int kk = 0; kk < BK; kk++) {
            float4 a4 = *(const float4*)&As [kk][ty * 4];
            float4 c4 = *(const float4*)&B1s[kk][tx * 4];
            float4 d4 = *(const float4*)&B2s[kk][tx * 4];
            float a[4] = {a4.x, a4.y, a4.z, a4.w};
            float c[4] = {c4.x, c4.y, c4.z, c4.w};
            float d[4] = {d4.x, d4.y, d4.z, d4.w};
#pragma unroll
            for (int i = 0; i < 4; i++)
#pragma unroll
                for (int j = 0; j < 4; j++) {
                    acc1[i][j] = fmaf(a[i], c[j], acc1[i][j]);
                    acc2[i][j] = fmaf(a[i], d[j], acc2[i][j]);
                }
        }
        __syncthreads();
    }

    // Epilogue: Q row-major
#pragma unroll
    for (int i = 0; i < 4; i++) {
        int m = m0 + ty * 4 + i;
        float4 v = make_float4(acc1[i][0], acc1[i][1], acc1[i][2], acc1[i][3]);
        *(float4*)&g_Q[m * Un + n0 + tx * 4] = v;
    }
    // Epilogue: KT[b][u][q] = K + bh. Tile never spans batches (64 | 256).
    {
        const int bidx = m0 >> 8;              // m0 / 256
        const int q0 = (m0 & 255) + ty * 4;    // aligned to 4
#pragma unroll
        for (int j = 0; j < 4; j++) {
            int u = n0 + tx * 4 + j;
            float bhv = __ldg(&bh[u]);
            float4 v = make_float4(acc2[0][j] + bhv, acc2[1][j] + bhv,
                                   acc2[2][j] + bhv, acc2[3][j] + bhv);
            *(float4*)&g_KT[(bidx * Un + u) * Ln + q0] = v;
        }
    }
}

// ---------------------------------------------------------------------------
// Kernel B: additive-attention core. One CTA handles PT=4 query rows p of one
// batch. Thread t <-> key index q=t. e-loop is MUFU(tanh)-bound; KT loads are
// coalesced (KT is [u][q]) and 4x-reused across the p-tile.
// ---------------------------------------------------------------------------
#define PT 4

__global__ __launch_bounds__(256) void attn_kernel(
    const float* __restrict__ X,    // inputs [8,256,512]
    const float* __restrict__ Wv,   // [512]
    float* __restrict__ out)        // [8,256,512]
{
    __shared__ float Qs[PT][Un];     // 8 KB
    __shared__ float Wvs[Un];        // 2 KB
    __shared__ float esm[PT][Ln];    // 4 KB

    const int tid = threadIdx.x;
    const int b  = blockIdx.x >> 6;          // 64 p-tiles per batch
    const int p0 = (blockIdx.x & 63) * PT;

    // Stage Q rows (contiguous) and Wv into smem
    {
        const float4* qsrc = (const float4*)&g_Q[(b * Ln + p0) * Un];
        float4* qdst = (float4*)&Qs[0][0];
#pragma unroll
        for (int i = tid; i < PT * Un / 4; i += 256) qdst[i] = qsrc[i];
        if (tid < Un / 4) ((float4*)Wvs)[tid] = ((const float4*)Wv)[tid];
    }
    __syncthreads();

    // e[p] for q = tid
    float e[PT];
#pragma unroll
    for (int p = 0; p < PT; p++) e[p] = 0.f;

    const float* kt = g_KT + b * Un * Ln;
#pragma unroll 4
    for (int u = 0; u < Un; u++) {
        float kv = kt[u * Ln + tid];
        float wv = Wvs[u];
#pragma unroll
        for (int p = 0; p < PT; p++) {
            e[p] = fmaf(wv, tanh_approx(Qs[p][u] + kv), e[p]);
        }
    }
    // NOTE: ba is a uniform shift of e -> cancels exactly in exp-normalize.

#pragma unroll
    for (int p = 0; p < PT; p++) esm[p][tid] = e[p];
    __syncthreads();

    // Warp w normalizes row p=w: max, exp, sum, scale by 1/(sum+eps)
    {
        const int w = tid >> 5, l = tid & 31;
        if (w < PT) {
            float m = -1e30f;
#pragma unroll
            for (int j = 0; j < 8; j++) m = fmaxf(m, esm[w][l + j * 32]);
#pragma unroll
            for (int o = 16; o > 0; o >>= 1)
                m = fmaxf(m, __shfl_xor_sync(0xffffffffu, m, o));
            float ex[8];
            float s = 0.f;
#pragma unroll
            for (int j = 0; j < 8; j++) {
                ex[j] = __expf(esm[w][l + j * 32] - m);
                s += ex[j];
            }
#pragma unroll
            for (int o = 16; o > 0; o >>= 1)
                s += __shfl_xor_sync(0xffffffffu, s, o);
            float inv = 1.f / (s + 1e-7f);
#pragma unroll
            for (int j = 0; j < 8; j++) esm[w][l + j * 32] = ex[j] * inv;
        }
    }
    __syncthreads();

    // out[p, f] = sum_q a[p][q] * X[b, q, f]; thread t covers f = t and t+256
    float acc0[PT], acc1[PT];
#pragma unroll
    for (int p = 0; p < PT; p++) { acc0[p] = 0.f; acc1[p] = 0.f; }

    const float* xin = X + b * Ln * Fn;
#pragma unroll 2
    for (int q = 0; q < Ln; q++) {
        float x0 = xin[q * Fn + tid];
        float x1 = xin[q * Fn + tid + 256];
#pragma unroll
        for (int p = 0; p < PT; p++) {
            float aq = esm[p][q];
            acc0[p] = fmaf(aq, x0, acc0[p]);
            acc1[p] = fmaf(aq, x1, acc1[p]);
        }
    }
#pragma unroll
    for (int p = 0; p < PT; p++) {
        out[(b * Ln + p0 + p) * Fn + tid]       = acc0[p];
        out[(b * Ln + p0 + p) * Fn + tid + 256] = acc1[p];
    }
}

extern "C" void kernel_launch(void* const* d_in, const int* in_sizes, int n_in,
                              void* d_out, int out_size) {
    const float* X  = (const float*)d_in[0];  // inputs
    const float* Wq = (const float*)d_in[1];
    const float* Wk = (const float*)d_in[2];
    const float* Wv = (const float*)d_in[3];
    const float* bh = (const float*)d_in[4];
    // d_in[5] = ba: cancels exactly in the exp-normalize; unused.
    float* out = (float*)d_out;

    dim3 gridA(Un / BN, Mn / BM);  // (8, 32)
    proj_kernel<<<gridA, 256>>>(X, Wq, Wk, bh);

    attn_kernel<<<Bn * (Ln / PT), 256>>>(X, Wv, out);
}

// round 2
// speedup vs baseline: 1.1955x; 1.1955x over previous
#include <cuda_runtime.h>

// Shapes (fixed): B=8, L=256, F=512, U=512.
// inputs [8,256,512], Wq [512,512], Wk [512,512], Wv [512,1], bh [512], ba [1]
// out [8,256,512] float32.

#define Bn 8
#define Ln 256
#define Fn 512
#define Un 512
#define Mn (Bn*Ln)   // 2048
#define PT 4
#define USPLIT 8
#define UCH (Un/USPLIT)   // 64

// Scratch: Q [2048,512] row-major, KT [8][512][256] (K + bh, transposed per batch)
__device__ __align__(16) float g_Q[Mn * Un];
__device__ __align__(16) float g_KT[Bn * Un * Ln];

__device__ __forceinline__ float tanh_approx(float x) {
    float y;
    asm("tanh.approx.f32 %0, %1;" : "=f"(y) : "f"(x));
    return y;
}

// ---------------------------------------------------------------------------
// Kernel A: dual SGEMM. Computes Q = X*Wq and KT = transpose(X*Wk + bh).
// ---------------------------------------------------------------------------
#define BM 64
#define BN 64
#define BK 16

__global__ __launch_bounds__(256) void proj_kernel(
    const float* __restrict__ X,    // [2048,512]
    const float* __restrict__ Wq,   // [512,512]
    const float* __restrict__ Wk,   // [512,512]
    const float* __restrict__ bh)   // [512]
{
    __shared__ float As[BK][BM];
    __shared__ float B1s[BK][BN];
    __shared__ float B2s[BK][BN];

    const int tid = threadIdx.x;
    const int tx = tid & 15;
    const int ty = tid >> 4;
    const int m0 = blockIdx.y * BM;
    const int n0 = blockIdx.x * BN;

    float acc1[4][4], acc2[4][4];
#pragma unroll
    for (int i = 0; i < 4; i++)
#pragma unroll
        for (int j = 0; j < 4; j++) { acc1[i][j] = 0.f; acc2[i][j] = 0.f; }

    const int a_row = tid >> 2;
    const int a_k4  = (tid & 3) * 4;
    const int b_k  = tid >> 4;
    const int b_n4 = (tid & 15) * 4;

    for (int k0 = 0; k0 < Fn; k0 += BK) {
        float4 av  = *(const float4*)&X [(m0 + a_row) * Fn + k0 + a_k4];
        float4 bv1 = *(const float4*)&Wq[(k0 + b_k) * Un + n0 + b_n4];
        float4 bv2 = *(const float4*)&Wk[(k0 + b_k) * Un + n0 + b_n4];

        As[a_k4 + 0][a_row] = av.x;
        As[a_k4 + 1][a_row] = av.y;
        As[a_k4 + 2][a_row] = av.z;
        As[a_k4 + 3][a_row] = av.w;
        *(float4*)&B1s[b_k][b_n4] = bv1;
        *(float4*)&B2s[b_k][b_n4] = bv2;
        __syncthreads();

#pragma unroll
        for (int kk = 0; kk < BK; kk++) {
            float4 a4 = *(const float4*)&As [kk][ty * 4];
            float4 c4 = *(const float4*)&B1s[kk][tx * 4];
            float4 d4 = *(const float4*)&B2s[kk][tx * 4];
            float a[4] = {a4.x, a4.y, a4.z, a4.w};
            float c[4] = {c4.x, c4.y, c4.z, c4.w};
            float d[4] = {d4.x, d4.y, d4.z, d4.w};
#pragma unroll
            for (int i = 0; i < 4; i++)
#pragma unroll
                for (int j = 0; j < 4; j++) {
                    acc1[i][j] = fmaf(a[i], c[j], acc1[i][j]);
                    acc2[i][j] = fmaf(a[i], d[j], acc2[i][j]);
                }
        }
        __syncthreads();
    }

#pragma unroll
    for (int i = 0; i < 4; i++) {
        int m = m0 + ty * 4 + i;
        float4 v = make_float4(acc1[i][0], acc1[i][1], acc1[i][2], acc1[i][3]);
        *(float4*)&g_Q[m * Un + n0 + tx * 4] = v;
    }
    {
        const int bidx = m0 >> 8;
        const int q0 = (m0 & 255) + ty * 4;
#pragma unroll
        for (int j = 0; j < 4; j++) {
            int u = n0 + tx * 4 + j;
            float bhv = __ldg(&bh[u]);
            float4 v = make_float4(acc2[0][j] + bhv, acc2[1][j] + bhv,
                                   acc2[2][j] + bhv, acc2[3][j] + bhv);
            *(float4*)&g_KT[(bidx * Un + u) * Ln + q0] = v;
        }
    }
}

// ---------------------------------------------------------------------------
// Kernel B: additive-attention core, MUFU-bound design.
// 512 threads/CTA. e-loop: thread = (us = tid>>6 of 8 u-splits, qg = tid&63 of
// 4-wide q groups). 16 tanh per iteration behind one LDG.128 + one LDS.128.
// Partial e reduced via smem; 4-way q-split vectorized epilogue.
// ---------------------------------------------------------------------------
__global__ __launch_bounds__(512) void attn_kernel(
    const float* __restrict__ X,    // inputs [8,256,512]
    const float* __restrict__ Wv,   // [512]
    float* __restrict__ out)        // [8,256,512]
{
    __shared__ float4 QsT[Un];        // [u] -> (Q[p0..p0+3][u])   8 KB
    __shared__ float  Wvs[Un];        // 2 KB
    __shared__ float  scratch[8192];  // 32 KB: epart[8][4][256] then opart[4][4][512]
    __shared__ float  aT[Ln * PT];    // [q][p]  4 KB

    const int tid = threadIdx.x;
    const int b  = blockIdx.x >> 6;
    const int p0 = (blockIdx.x & 63) * PT;

    // Stage Q transposed: QsT[u] = {Q[p0][u], Q[p0+1][u], Q[p0+2][u], Q[p0+3][u]}
    {
        float* qst = (float*)QsT;
#pragma unroll
        for (int i = tid; i < PT * Un; i += 512) {
            int p = i >> 9;          // 0..3
            int u = i & 511;
            qst[u * 4 + p] = g_Q[(b * Ln + p0 + p) * Un + u];
        }
        Wvs[tid] = Wv[tid];          // Un == blockDim == 512
    }
    __syncthreads();

    // ---- e-loop: 16 tanh / iter / thread ----
    const int us = tid >> 6;         // 0..7
    const int qg = tid & 63;         // 0..63 (covers q = qg*4 .. qg*4+3)
    const float4* __restrict__ kt4 = (const float4*)(g_KT + (size_t)b * Un * Ln);

    float4 e0 = make_float4(0.f,0.f,0.f,0.f), e1 = e0, e2 = e0, e3 = e0;
    const int u0 = us * UCH;
#pragma unroll 4
    for (int i = 0; i < UCH; i++) {
        const int u = u0 + i;
        float4 kv = __ldg(&kt4[u * 64 + qg]);
        float4 q4 = QsT[u];
        float  wv = Wvs[u];
        e0.x = fmaf(wv, tanh_approx(q4.x + kv.x), e0.x);
        e0.y = fmaf(wv, tanh_approx(q4.x + kv.y), e0.y);
        e0.z = fmaf(wv, tanh_approx(q4.x + kv.z), e0.z);
        e0.w = fmaf(wv, tanh_approx(q4.x + kv.w), e0.w);
        e1.x = fmaf(wv, tanh_approx(q4.y + kv.x), e1.x);
        e1.y = fmaf(wv, tanh_approx(q4.y + kv.y), e1.y);
        e1.z = fmaf(wv, tanh_approx(q4.y + kv.z), e1.z);
        e1.w = fmaf(wv, tanh_approx(q4.y + kv.w), e1.w);
        e2.x = fmaf(wv, tanh_approx(q4.z + kv.x), e2.x);
        e2.y = fmaf(wv, tanh_approx(q4.z + kv.y), e2.y);
        e2.z = fmaf(wv, tanh_approx(q4.z + kv.z), e2.z);
        e2.w = fmaf(wv, tanh_approx(q4.z + kv.w), e2.w);
        e3.x = fmaf(wv, tanh_approx(q4.w + kv.x), e3.x);
        e3.y = fmaf(wv, tanh_approx(q4.w + kv.y), e3.y);
        e3.z = fmaf(wv, tanh_approx(q4.w + kv.z), e3.z);
        e3.w = fmaf(wv, tanh_approx(q4.w + kv.w), e3.w);
    }
    // ba is a uniform shift of e -> cancels exactly in the exp-normalize.

    // Store partials: epart[us][p][q] (float4 view [8][4][64])
    {
        float4* ep4 = (float4*)scratch;
        ep4[(us * 4 + 0) * 64 + qg] = e0;
        ep4[(us * 4 + 1) * 64 + qg] = e1;
        ep4[(us * 4 + 2) * 64 + qg] = e2;
        ep4[(us * 4 + 3) * 64 + qg] = e3;
    }
    __syncthreads();

    // Reduce 8 u-split partials -> aT[q][p] (pre-normalization scores)
#pragma unroll
    for (int idx = tid; idx < PT * Ln; idx += 512) {
        int p = idx >> 8;
        int q = idx & 255;
        float s = 0.f;
#pragma unroll
        for (int u = 0; u < USPLIT; u++)
            s += scratch[(u * 4 + p) * 256 + q];
        aT[q * 4 + p] = s;
    }
    __syncthreads();

    // Normalize rows in place: warp w handles row p = w (w < 4)
    {
        const int w = tid >> 5, l = tid & 31;
        if (w < PT) {
            float m = -1e30f;
#pragma unroll
            for (int j = 0; j < 8; j++) m = fmaxf(m, aT[(l + j * 32) * 4 + w]);
#pragma unroll
            for (int o = 16; o > 0; o >>= 1)
                m = fmaxf(m, __shfl_xor_sync(0xffffffffu, m, o));
            float ex[8];
            float s = 0.f;
#pragma unroll
            for (int j = 0; j < 8; j++) {
                ex[j] = __expf(aT[(l + j * 32) * 4 + w] - m);
                s += ex[j];
            }
#pragma unroll
            for (int o = 16; o > 0; o >>= 1)
                s += __shfl_xor_sync(0xffffffffu, s, o);
            float inv = 1.f / (s + 1e-7f);
#pragma unroll
            for (int j = 0; j < 8; j++) aT[(l + j * 32) * 4 + w] = ex[j] * inv;
        }
    }
    __syncthreads();

    // ---- epilogue: out[p,f] = sum_q a[p][q] * X[b,q,f], 4-way q-split ----
    const int qs = tid >> 7;     // 0..3
    const int fg = tid & 127;    // float4 group over f
    const float4* __restrict__ xin4 = (const float4*)(X + (size_t)b * Ln * Fn);

    float4 o0 = make_float4(0.f,0.f,0.f,0.f), o1 = o0, o2 = o0, o3 = o0;
#pragma unroll 4
    for (int i = 0; i < Ln / 4; i++) {
        const int q = qs * 64 + i;
        float4 x4 = __ldg(&xin4[q * 128 + fg]);
        float4 a4 = *(const float4*)&aT[q * 4];   // warp-uniform broadcast
        o0.x = fmaf(a4.x, x4.x, o0.x); o0.y = fmaf(a4.x, x4.y, o0.y);
        o0.z = fmaf(a4.x, x4.z, o0.z); o0.w = fmaf(a4.x, x4.w, o0.w);
        o1.x = fmaf(a4.y, x4.x, o1.x); o1.y = fmaf(a4.y, x4.y, o1.y);
        o1.z = fmaf(a4.y, x4.z, o1.z); o1.w = fmaf(a4.y, x4.w, o1.w);
        o2.x = fmaf(a4.z, x4.x, o2.x); o2.y = fmaf(a4.z, x4.y, o2.y);
        o2.z = fmaf(a4.z, x4.z, o2.z); o2.w = fmaf(a4.z, x4.w, o2.w);
        o3.x = fmaf(a4.w, x4.x, o3.x); o3.y = fmaf(a4.w, x4.y, o3.y);
        o3.z = fmaf(a4.w, x4.z, o3.z); o3.w = fmaf(a4.w, x4.w, o3.w);
    }
    // opart[qs][p][f] (float4 view [4][4][128]) -- reuses scratch (safe: synced)
    {
        float4* op4 = (float4*)scratch;
        op4[(qs * 4 + 0) * 128 + fg] = o0;
        op4[(qs * 4 + 1) * 128 + fg] = o1;
        op4[(qs * 4 + 2) * 128 + fg] = o2;
        op4[(qs * 4 + 3) * 128 + fg] = o3;
    }
    __syncthreads();

    // Final reduce over 4 q-splits and store
    {
        const int f = tid;
#pragma unroll
        for (int p = 0; p < PT; p++) {
            float s = scratch[(0 * 4 + p) * 512 + f]
                    + scratch[(1 * 4 + p) * 512 + f]
                    + scratch[(2 * 4 + p) * 512 + f]
                    + scratch[(3 * 4 + p) * 512 + f];
            out[(size_t)(b * Ln + p0 + p) * Fn + f] = s;
        }
    }
}

extern "C" void kernel_launch(void* const* d_in, const int* in_sizes, int n_in,
                              void* d_out, int out_size) {
    const float* X  = (const float*)d_in[0];
    const float* Wq = (const float*)d_in[1];
    const float* Wk = (const float*)d_in[2];
    const float* Wv = (const float*)d_in[3];
    const float* bh = (const float*)d_in[4];
    // d_in[5] = ba: cancels exactly in the exp-normalize; unused.
    float* out = (float*)d_out;

    dim3 gridA(Un / BN, Mn / BM);  // (8, 32)
    proj_kernel<<<gridA, 256>>>(X, Wq, Wk, bh);

    attn_kernel<<<Bn * (Ln / PT), 512>>>(X, Wv, out);
}